// round 2
// baseline (speedup 1.0000x reference)
#include <cuda_runtime.h>
#include <math.h>

// Shapes fixed by the problem.
#define BB 16
#define SS 2048
#define DD 768
#define BSD (BB*SS*DD)

// Scratch (no cudaMalloc allowed): alphas + prefix sums in double, fused weights.
__device__ double g_alpha[BB*SS];
__device__ double g_A[BB*SS];
__device__ float  g_weff[3*DD];   // layout [k*DD + i], computed in double then rounded once
__device__ double g_beff;

// ---------------------------------------------------------------------------
// Kernel 1: fold Linear into Conv.
//   w_eff[k,i] = sum_o lin_w[o] * conv_w[o,i,k]   (double accumulate)
//   b_eff     = lin_b + sum_o lin_w[o] * conv_b[o]
// conv_w layout: (O, I, K) row-major -> conv_w[o*(DD*3) + i*3 + k]
// ---------------------------------------------------------------------------
__global__ void k_prep(const float* __restrict__ conv_w,
                       const float* __restrict__ conv_b,
                       const float* __restrict__ lin_w,
                       const float* __restrict__ lin_b)
{
    int t = blockIdx.x * blockDim.x + threadIdx.x;   // 0 .. 3*DD-1
    if (t < 3*DD) {
        int k = t / DD;
        int i = t - k * DD;
        int base = i * 3 + k;
        double acc = 0.0;
        #pragma unroll 8
        for (int o = 0; o < DD; o++)
            acc += (double)lin_w[o] * (double)conv_w[o * (DD*3) + base];
        g_weff[t] = (float)acc;
    }
    if (blockIdx.x == 0 && threadIdx.x < 32) {
        int l = threadIdx.x;
        double acc = 0.0;
        for (int o = l; o < DD; o += 32)
            acc += (double)lin_w[o] * (double)conv_b[o];
        #pragma unroll
        for (int off = 16; off; off >>= 1)
            acc += __shfl_down_sync(0xffffffffu, acc, off);
        if (l == 0) g_beff = acc + (double)lin_b[0];
    }
}

// ---------------------------------------------------------------------------
// Kernel 2: alpha[b,s] = sigmoid( b_eff + sum_k sum_i w_eff[k,i]*x[b,s-1+k,i] )
// One warp per (b,s). fp32 products, fp64 accumulation in chunks of 8.
// alpha masked to 0 for s >= len[b].
// ---------------------------------------------------------------------------
__global__ void k_alpha(const float* __restrict__ x, const int* __restrict__ lens)
{
    __shared__ float sw[3*DD];
    for (int i = threadIdx.x; i < 3*DD; i += blockDim.x) sw[i] = g_weff[i];
    __syncthreads();

    int b    = blockIdx.y;
    int s    = blockIdx.x * 8 + (threadIdx.x >> 5);
    int lane = threadIdx.x & 31;
    const float* xb = x + (size_t)b * SS * DD;

    double dacc = 0.0;
    #pragma unroll
    for (int k = 0; k < 3; k++) {
        int t = s - 1 + k;
        if ((unsigned)t < (unsigned)SS) {
            const float* row = xb + (size_t)t * DD;
            const float* swk = sw + k * DD;
            #pragma unroll
            for (int c = 0; c < 3; c++) {           // 3 chunks of 8 -> 24 = DD/32
                float f = 0.0f;
                #pragma unroll
                for (int j = 0; j < 8; j++) {
                    int i = lane + 32 * (c * 8 + j);
                    f = fmaf(swk[i], row[i], f);
                }
                dacc += (double)f;
            }
        }
    }
    #pragma unroll
    for (int off = 16; off; off >>= 1)
        dacc += __shfl_down_sync(0xffffffffu, dacc, off);

    if (lane == 0) {
        double z = dacc + g_beff;
        double a = (s < lens[b]) ? (1.0 / (1.0 + exp(-z))) : 0.0;
        g_alpha[b * SS + s] = a;
    }
}

// ---------------------------------------------------------------------------
// Kernel 3: per-batch inclusive prefix sum of alpha (double). One block/batch.
// Also writes len_tensor = floor(A[S-1]) as float at out[BSD + b] if it fits.
// ---------------------------------------------------------------------------
__global__ void k_scan(float* __restrict__ out, int out_size)
{
    __shared__ double sa[SS];
    __shared__ double sp[SS/2];
    int b   = blockIdx.x;
    int tid = threadIdx.x;          // 1024 threads, 2 elems each

    sa[2*tid]     = g_alpha[b*SS + 2*tid];
    sa[2*tid + 1] = g_alpha[b*SS + 2*tid + 1];
    __syncthreads();

    double a1 = sa[2*tid + 1];
    sp[tid] = sa[2*tid] + a1;
    __syncthreads();

    for (int off = 1; off < SS/2; off <<= 1) {
        double t = 0.0;
        if (tid >= off) t = sp[tid - off];
        __syncthreads();
        if (tid >= off) sp[tid] += t;
        __syncthreads();
    }
    double incl = sp[tid];                 // A[2*tid + 1]
    g_A[b*SS + 2*tid]     = incl - a1;     // A[2*tid]
    g_A[b*SS + 2*tid + 1] = incl;

    if (tid == SS/2 - 1) {
        int n = (int)floor(incl);
        if (BSD + b < out_size) out[BSD + b] = (float)n;
    }
}

// ---------------------------------------------------------------------------
// Kernel 4: output rows. One warp per (b, k).
//   k >= n          -> zeros
//   k <  n          -> c_k = sum_t ( min(A_t,k+1) - max(A_{t-1},k) ) * h_t
// over the (binary-searched) step range covering A-interval (k, k+1].
// ---------------------------------------------------------------------------
__global__ void k_gather(const float* __restrict__ x, float* __restrict__ out)
{
    int b    = blockIdx.y;
    int k    = blockIdx.x * 8 + (threadIdx.x >> 5);
    int lane = threadIdx.x & 31;

    const double* A = g_A + (size_t)b * SS;
    int n = (int)floor(A[SS - 1]);

    float4* orow = (float4*)(out + ((size_t)(b * SS + k)) * DD);

    if (k >= n) {
        float4 z = make_float4(0.f, 0.f, 0.f, 0.f);
        #pragma unroll
        for (int j = 0; j < DD/128; j++) orow[lane + 32*j] = z;
        return;
    }

    double kd = (double)k, kp1 = kd + 1.0;

    // t_hi: first t with A[t] >= k+1 (exists: A[S-1] >= n >= k+1)
    int lo = 0, hi = SS - 1;
    while (lo < hi) { int m = (lo + hi) >> 1; if (A[m] >= kp1) hi = m; else lo = m + 1; }
    int t_hi = lo;
    // t_lo: first t with A[t] > k
    lo = 0; hi = t_hi;
    while (lo < hi) { int m = (lo + hi) >> 1; if (A[m] > kd) hi = m; else lo = m + 1; }
    int t_lo = lo;

    float4 acc[DD/128];
    #pragma unroll
    for (int j = 0; j < DD/128; j++) acc[j] = make_float4(0.f, 0.f, 0.f, 0.f);

    double Ap = (t_lo > 0) ? A[t_lo - 1] : 0.0;
    const float4* xb = (const float4*)(x + (size_t)b * SS * DD);

    for (int t = t_lo; t <= t_hi; t++) {
        double At = A[t];
        float w = (float)(fmin(At, kp1) - fmax(Ap, kd));
        Ap = At;
        const float4* row = xb + (size_t)t * (DD/4);
        #pragma unroll
        for (int j = 0; j < DD/128; j++) {
            float4 v = row[lane + 32*j];
            acc[j].x = fmaf(w, v.x, acc[j].x);
            acc[j].y = fmaf(w, v.y, acc[j].y);
            acc[j].z = fmaf(w, v.z, acc[j].z);
            acc[j].w = fmaf(w, v.w, acc[j].w);
        }
    }
    #pragma unroll
    for (int j = 0; j < DD/128; j++) orow[lane + 32*j] = acc[j];
}

// ---------------------------------------------------------------------------
extern "C" void kernel_launch(void* const* d_in, const int* in_sizes, int n_in,
                              void* d_out, int out_size)
{
    const float* x      = (const float*)d_in[0];   // (B,S,D)
    const int*   lens   = (const int*)  d_in[1];   // (B,)
    const float* conv_w = (const float*)d_in[2];   // (D,D,3)
    const float* conv_b = (const float*)d_in[3];   // (D,)
    const float* lin_w  = (const float*)d_in[4];   // (1,D)
    const float* lin_b  = (const float*)d_in[5];   // (1,)
    float* out = (float*)d_out;

    k_prep<<<(3*DD + 255)/256, 256>>>(conv_w, conv_b, lin_w, lin_b);
    dim3 grid(SS/8, BB);
    k_alpha<<<grid, 256>>>(x, lens);
    k_scan<<<BB, SS/2>>>(out, out_size);
    k_gather<<<grid, 256>>>(x, out);
}

// round 3
// speedup vs baseline: 1.6978x; 1.6978x over previous
#include <cuda_runtime.h>
#include <math.h>

// Shapes fixed by the problem.
#define BB 16
#define SS 2048
#define DD 768
#define BSD (BB*SS*DD)

// Scratch (no cudaMalloc allowed).
__device__ double g_dots[(size_t)BB*SS*3];  // per-row dots with w0,w1,w2 (interleaved)
__device__ double g_A[BB*SS];               // per-batch inclusive prefix sums of alpha
__device__ float  g_weff[3*DD];             // fused conv+linear weights, layout [k*DD + i]
__device__ double g_beff;

// ---------------------------------------------------------------------------
// Kernel 1: fold Linear into Conv (coalesced matvec, fp32 chunk accumulation).
//   w_eff[k,i] = sum_o lin_w[o] * conv_w[o, i, k]
//   b_eff     = lin_b + sum_o lin_w[o] * conv_b[o]
// conv_w layout: (O, I, K) row-major -> conv_w[o*(DD*3) + i*3 + k]
// Thread handles column c = i*3+k of conv_w (coalesced across threads).
// ---------------------------------------------------------------------------
__global__ void k_prep(const float* __restrict__ conv_w,
                       const float* __restrict__ conv_b,
                       const float* __restrict__ lin_w,
                       const float* __restrict__ lin_b)
{
    __shared__ float slw[DD];
    for (int i = threadIdx.x; i < DD; i += blockDim.x) slw[i] = lin_w[i];
    __syncthreads();

    int c = blockIdx.x * blockDim.x + threadIdx.x;   // 0 .. 3*DD-1
    if (c < 3*DD) {
        double acc = 0.0;
        #pragma unroll 8
        for (int o8 = 0; o8 < DD; o8 += 8) {
            float f = 0.0f;
            #pragma unroll
            for (int j = 0; j < 8; j++) {
                int o = o8 + j;
                f = fmaf(slw[o], conv_w[o * (3*DD) + c], f);
            }
            acc += (double)f;
        }
        int i = c / 3, k = c - 3*i;
        g_weff[k*DD + i] = (float)acc;
    }
    if (blockIdx.x == 0 && threadIdx.x < 32) {
        int l = threadIdx.x;
        double acc = 0.0;
        for (int o = l; o < DD; o += 32)
            acc += (double)lin_w[o] * (double)conv_b[o];
        #pragma unroll
        for (int off = 16; off; off >>= 1)
            acc += __shfl_down_sync(0xffffffffu, acc, off);
        if (l == 0) g_beff = acc + (double)lin_b[0];
    }
}

// ---------------------------------------------------------------------------
// Kernel 2: per-row dots. One warp per (b,t):
//   d_k[b,t] = dot(w_k, x[b,t,:])   k = 0,1,2   (x read ONCE)
// fp32 products in chunks of 8, fp64 chunk + warp reduction.
// ---------------------------------------------------------------------------
__global__ void k_dots(const float* __restrict__ x)
{
    __shared__ float4 sw[3*DD/4];
    for (int i = threadIdx.x; i < 3*DD/4; i += blockDim.x)
        sw[i] = ((const float4*)g_weff)[i];
    __syncthreads();

    int b    = blockIdx.y;
    int t    = blockIdx.x * 8 + (threadIdx.x >> 5);
    int lane = threadIdx.x & 31;
    const float4* row = (const float4*)(x + ((size_t)b * SS + t) * DD);

    double d0 = 0.0, d1 = 0.0, d2 = 0.0;
    #pragma unroll
    for (int m = 0; m < 6; m += 2) {            // 6 float4 per lane, chunks of 2 (=8 floats)
        float f0 = 0.f, f1 = 0.f, f2 = 0.f;
        #pragma unroll
        for (int mm = m; mm < m + 2; mm++) {
            int idx = lane + 32 * mm;
            float4 v  = row[idx];
            float4 w0 = sw[idx];
            float4 w1 = sw[DD/4 + idx];
            float4 w2 = sw[2*(DD/4) + idx];
            f0 = fmaf(w0.x, v.x, fmaf(w0.y, v.y, fmaf(w0.z, v.z, fmaf(w0.w, v.w, f0))));
            f1 = fmaf(w1.x, v.x, fmaf(w1.y, v.y, fmaf(w1.z, v.z, fmaf(w1.w, v.w, f1))));
            f2 = fmaf(w2.x, v.x, fmaf(w2.y, v.y, fmaf(w2.z, v.z, fmaf(w2.w, v.w, f2))));
        }
        d0 += (double)f0; d1 += (double)f1; d2 += (double)f2;
    }
    #pragma unroll
    for (int off = 16; off; off >>= 1) {
        d0 += __shfl_down_sync(0xffffffffu, d0, off);
        d1 += __shfl_down_sync(0xffffffffu, d1, off);
        d2 += __shfl_down_sync(0xffffffffu, d2, off);
    }
    if (lane == 0) {
        double* o = g_dots + ((size_t)b * SS + t) * 3;
        o[0] = d0; o[1] = d1; o[2] = d2;
    }
}

// ---------------------------------------------------------------------------
// Kernel 3: fused alpha + per-batch prefix sum. One block/batch.
//   logit[s] = b_eff + d0[s-1] + d1[s] + d2[s+1]   (boundary terms dropped)
//   alpha[s] = (s < len) ? sigmoid(logit) : 0
// Hillis-Steele scan in double. Writes len_tensor at out[BSD + b].
// ---------------------------------------------------------------------------
__global__ void k_scan(const int* __restrict__ lens, float* __restrict__ out, int out_size)
{
    __shared__ double sa[SS];
    __shared__ double sp[SS/2];
    int b   = blockIdx.x;
    int tid = threadIdx.x;          // 1024 threads, 2 elems each
    int len = lens[b];
    const double* d = g_dots + (size_t)b * SS * 3;
    double beff = g_beff;

    #pragma unroll
    for (int e = 0; e < 2; e++) {
        int s = 2*tid + e;
        double z = beff + d[3*s + 1];
        if (s > 0)      z += d[3*(s-1) + 0];
        if (s < SS-1)   z += d[3*(s+1) + 2];
        sa[s] = (s < len) ? (1.0 / (1.0 + exp(-z))) : 0.0;
    }
    __syncthreads();

    double a1 = sa[2*tid + 1];
    sp[tid] = sa[2*tid] + a1;
    __syncthreads();

    for (int off = 1; off < SS/2; off <<= 1) {
        double t = 0.0;
        if (tid >= off) t = sp[tid - off];
        __syncthreads();
        if (tid >= off) sp[tid] += t;
        __syncthreads();
    }
    double incl = sp[tid];                 // A[2*tid + 1]
    g_A[b*SS + 2*tid]     = incl - a1;     // A[2*tid]
    g_A[b*SS + 2*tid + 1] = incl;

    if (tid == SS/2 - 1) {
        int n = (int)floor(incl);
        if (BSD + b < out_size) out[BSD + b] = (float)n;
    }
}

// ---------------------------------------------------------------------------
// Kernel 4: output rows. One warp per (b, k).
//   k >= n -> zeros
//   k <  n -> c_k = sum_t ( min(A_t,k+1) - max(A_{t-1},k) ) * h_t
// over the (binary-searched) step range covering A-interval (k, k+1].
// ---------------------------------------------------------------------------
__global__ void k_gather(const float* __restrict__ x, float* __restrict__ out)
{
    int b    = blockIdx.y;
    int k    = blockIdx.x * 8 + (threadIdx.x >> 5);
    int lane = threadIdx.x & 31;

    const double* A = g_A + (size_t)b * SS;
    int n = (int)floor(A[SS - 1]);

    float4* orow = (float4*)(out + ((size_t)(b * SS + k)) * DD);

    if (k >= n) {
        float4 z = make_float4(0.f, 0.f, 0.f, 0.f);
        #pragma unroll
        for (int j = 0; j < DD/128; j++) orow[lane + 32*j] = z;
        return;
    }

    double kd = (double)k, kp1 = kd + 1.0;

    // t_hi: first t with A[t] >= k+1 (exists: A[S-1] >= n >= k+1)
    int lo = 0, hi = SS - 1;
    while (lo < hi) { int m = (lo + hi) >> 1; if (A[m] >= kp1) hi = m; else lo = m + 1; }
    int t_hi = lo;
    // t_lo: first t with A[t] > k
    lo = 0; hi = t_hi;
    while (lo < hi) { int m = (lo + hi) >> 1; if (A[m] > kd) hi = m; else lo = m + 1; }
    int t_lo = lo;

    float4 acc[DD/128];
    #pragma unroll
    for (int j = 0; j < DD/128; j++) acc[j] = make_float4(0.f, 0.f, 0.f, 0.f);

    double Ap = (t_lo > 0) ? A[t_lo - 1] : 0.0;
    const float4* xb = (const float4*)(x + (size_t)b * SS * DD);

    for (int t = t_lo; t <= t_hi; t++) {
        double At = A[t];
        float w = (float)(fmin(At, kp1) - fmax(Ap, kd));
        Ap = At;
        const float4* row = xb + (size_t)t * (DD/4);
        #pragma unroll
        for (int j = 0; j < DD/128; j++) {
            float4 v = row[lane + 32*j];
            acc[j].x = fmaf(w, v.x, acc[j].x);
            acc[j].y = fmaf(w, v.y, acc[j].y);
            acc[j].z = fmaf(w, v.z, acc[j].z);
            acc[j].w = fmaf(w, v.w, acc[j].w);
        }
    }
    #pragma unroll
    for (int j = 0; j < DD/128; j++) orow[lane + 32*j] = acc[j];
}

// ---------------------------------------------------------------------------
extern "C" void kernel_launch(void* const* d_in, const int* in_sizes, int n_in,
                              void* d_out, int out_size)
{
    const float* x      = (const float*)d_in[0];   // (B,S,D)
    const int*   lens   = (const int*)  d_in[1];   // (B,)
    const float* conv_w = (const float*)d_in[2];   // (D,D,3)
    const float* conv_b = (const float*)d_in[3];   // (D,)
    const float* lin_w  = (const float*)d_in[4];   // (1,D)
    const float* lin_b  = (const float*)d_in[5];   // (1,)
    float* out = (float*)d_out;

    k_prep<<<(3*DD + 255)/256, 256>>>(conv_w, conv_b, lin_w, lin_b);
    dim3 grid(SS/8, BB);
    k_dots<<<grid, 256>>>(x);
    k_scan<<<BB, SS/2>>>(lens, out, out_size);
    k_gather<<<grid, 256>>>(x, out);
}

// round 6
// speedup vs baseline: 2.0189x; 1.1892x over previous
#include <cuda_runtime.h>
#include <math.h>

// Shapes fixed by the problem.
#define BB 16
#define SS 2048
#define DD 768
#define BSD (BB*SS*DD)

// Scratch (no cudaMalloc allowed).
__device__ double g_dots[(size_t)BB*SS*3];  // per-row dots with w0,w1,w2 (interleaved)
__device__ double g_A[BB*SS];               // per-batch inclusive prefix sums of alpha
__device__ float  g_weff[3*DD];             // fused conv+linear weights, layout [k*DD + i]
__device__ double g_beff;

// ---------------------------------------------------------------------------
// Kernel 1: fold Linear into Conv.
//   w_eff[k,i] = sum_o lin_w[o] * conv_w[o, i, k]
// conv_w layout: (O, I, K) row-major -> column c = i*3+k at conv_w[o*(3*DD) + c].
// Block = 32 columns x 8 o-parts (256 thr). Each part sums 96 o's in fp32
// chunks of 8 -> fp64; parts reduced in order via shared (deterministic).
// Grid = 3*DD/32 = 72 blocks.
// ---------------------------------------------------------------------------
__global__ void k_prep(const float* __restrict__ conv_w,
                       const float* __restrict__ conv_b,
                       const float* __restrict__ lin_w,
                       const float* __restrict__ lin_b)
{
    __shared__ float  slw[DD];
    __shared__ double spart[8][32];
    int tid = threadIdx.x;
    for (int i = tid; i < DD; i += blockDim.x) slw[i] = lin_w[i];
    __syncthreads();

    int lane = tid & 31;
    int part = tid >> 5;                 // 0..7
    int c    = blockIdx.x * 32 + lane;   // column of conv_w

    double acc = 0.0;
    int o0 = part * (DD/8);              // 96 o's per part
    #pragma unroll 2
    for (int o8 = o0; o8 < o0 + DD/8; o8 += 8) {
        float f = 0.0f;
        #pragma unroll
        for (int j = 0; j < 8; j++)
            f = fmaf(slw[o8 + j], conv_w[(size_t)(o8 + j) * (3*DD) + c], f);
        acc += (double)f;
    }
    spart[part][lane] = acc;
    __syncthreads();

    if (part == 0) {
        double s = 0.0;
        #pragma unroll
        for (int p = 0; p < 8; p++) s += spart[p][lane];
        int i = c / 3, k = c - 3*i;
        g_weff[k*DD + i] = (float)s;
    }
    if (blockIdx.x == 0 && part == 1) {   // bias on a different warp
        double acc2 = 0.0;
        for (int o = lane; o < DD; o += 32)
            acc2 += (double)lin_w[o] * (double)conv_b[o];
        #pragma unroll
        for (int off = 16; off; off >>= 1)
            acc2 += __shfl_down_sync(0xffffffffu, acc2, off);
        if (lane == 0) g_beff = acc2 + (double)lin_b[0];
    }
}

// ---------------------------------------------------------------------------
// Kernel 2: per-row dots. One warp per (b,t):
//   d_k[b,t] = dot(w_k, x[b,t,:])   k = 0,1,2   (x read ONCE)
// All 6 float4 global loads issued up front (MLP=6), then fp32 chunks of 8
// -> fp64, warp reduce in double. Same FMA order as round-2 passing kernel.
// ---------------------------------------------------------------------------
__global__ void k_dots(const float* __restrict__ x)
{
    __shared__ float4 sw[3*DD/4];
    for (int i = threadIdx.x; i < 3*DD/4; i += blockDim.x)
        sw[i] = ((const float4*)g_weff)[i];
    __syncthreads();

    int b    = blockIdx.y;
    int t    = blockIdx.x * 8 + (threadIdx.x >> 5);
    int lane = threadIdx.x & 31;
    const float4* row = (const float4*)(x + ((size_t)b * SS + t) * DD);

    float4 v[6];
    #pragma unroll
    for (int m = 0; m < 6; m++) v[m] = row[lane + 32*m];

    double d0 = 0.0, d1 = 0.0, d2 = 0.0;
    #pragma unroll
    for (int m = 0; m < 6; m += 2) {            // chunks of 2 float4 = 8 floats
        float f0 = 0.f, f1 = 0.f, f2 = 0.f;
        #pragma unroll
        for (int mm = m; mm < m + 2; mm++) {
            int idx = lane + 32 * mm;
            float4 w0 = sw[idx];
            float4 w1 = sw[DD/4 + idx];
            float4 w2 = sw[2*(DD/4) + idx];
            f0 = fmaf(w0.x, v[mm].x, fmaf(w0.y, v[mm].y, fmaf(w0.z, v[mm].z, fmaf(w0.w, v[mm].w, f0))));
            f1 = fmaf(w1.x, v[mm].x, fmaf(w1.y, v[mm].y, fmaf(w1.z, v[mm].z, fmaf(w1.w, v[mm].w, f1))));
            f2 = fmaf(w2.x, v[mm].x, fmaf(w2.y, v[mm].y, fmaf(w2.z, v[mm].z, fmaf(w2.w, v[mm].w, f2))));
        }
        d0 += (double)f0; d1 += (double)f1; d2 += (double)f2;
    }
    #pragma unroll
    for (int off = 16; off; off >>= 1) {
        d0 += __shfl_down_sync(0xffffffffu, d0, off);
        d1 += __shfl_down_sync(0xffffffffu, d1, off);
        d2 += __shfl_down_sync(0xffffffffu, d2, off);
    }
    if (lane == 0) {
        double* o = g_dots + ((size_t)b * SS + t) * 3;
        o[0] = d0; o[1] = d1; o[2] = d2;
    }
}

// ---------------------------------------------------------------------------
// Kernel 3: fused alpha + per-batch prefix sum (shuffle scan). One block/batch.
//   logit[s] = b_eff + d0[s-1] + d1[s] + d2[s+1]
//   alpha[s] = (s < len) ? sigmoid(logit) : 0
// Each of 1024 threads owns 2 consecutive elems; warp Kogge-Stone scan over
// pair sums, warp aggregates scanned by warp 0. 2 barriers total.
// ---------------------------------------------------------------------------
__global__ void k_scan(const int* __restrict__ lens, float* __restrict__ out, int out_size)
{
    __shared__ double swarp[32];
    int b    = blockIdx.x;
    int tid  = threadIdx.x;          // 0..1023
    int lane = tid & 31;
    int wid  = tid >> 5;
    int len  = lens[b];
    const double* d = g_dots + (size_t)b * SS * 3;
    double beff = g_beff;

    double a[2];
    #pragma unroll
    for (int e = 0; e < 2; e++) {
        int s = 2*tid + e;
        double z = beff + d[3*s + 1];
        if (s > 0)      z += d[3*(s-1) + 0];
        if (s < SS-1)   z += d[3*(s+1) + 2];
        a[e] = (s < len) ? (1.0 / (1.0 + exp(-z))) : 0.0;
    }
    double psum = a[0] + a[1];

    // inclusive warp scan of psum
    #pragma unroll
    for (int off = 1; off < 32; off <<= 1) {
        double tmp = __shfl_up_sync(0xffffffffu, psum, off);
        if (lane >= off) psum += tmp;
    }
    if (lane == 31) swarp[wid] = psum;
    __syncthreads();
    if (wid == 0) {
        double v = swarp[lane];
        #pragma unroll
        for (int off = 1; off < 32; off <<= 1) {
            double tmp = __shfl_up_sync(0xffffffffu, v, off);
            if (lane >= off) v += tmp;
        }
        swarp[lane] = v;
    }
    __syncthreads();

    double base = (wid > 0) ? swarp[wid - 1] : 0.0;
    double incl = base + psum;             // A[2*tid + 1]
    g_A[b*SS + 2*tid]     = incl - a[1];   // A[2*tid]
    g_A[b*SS + 2*tid + 1] = incl;

    if (tid == SS/2 - 1) {
        int n = (int)floor(incl);
        if (BSD + b < out_size) out[BSD + b] = (float)n;
    }
}

// ---------------------------------------------------------------------------
// Kernel 4: output rows. One warp per (b, k).
//   k >= n -> zeros
//   k <  n -> c_k = sum_t ( min(A_t,k+1) - max(A_{t-1},k) ) * h_t
// ---------------------------------------------------------------------------
__global__ void __launch_bounds__(256, 4)
k_gather(const float* __restrict__ x, float* __restrict__ out)
{
    int b    = blockIdx.y;
    int k    = blockIdx.x * 8 + (threadIdx.x >> 5);
    int lane = threadIdx.x & 31;

    const double* A = g_A + (size_t)b * SS;
    int n = (int)floor(A[SS - 1]);

    float4* orow = (float4*)(out + ((size_t)(b * SS + k)) * DD);

    if (k >= n) {
        float4 z = make_float4(0.f, 0.f, 0.f, 0.f);
        #pragma unroll
        for (int j = 0; j < DD/128; j++) orow[lane + 32*j] = z;
        return;
    }

    double kd = (double)k, kp1 = kd + 1.0;

    // t_hi: first t with A[t] >= k+1 (exists: A[S-1] >= n >= k+1)
    int lo = 0, hi = SS - 1;
    while (lo < hi) { int m = (lo + hi) >> 1; if (A[m] >= kp1) hi = m; else lo = m + 1; }
    int t_hi = lo;
    // t_lo: first t with A[t] > k
    lo = 0; hi = t_hi;
    while (lo < hi) { int m = (lo + hi) >> 1; if (A[m] > kd) hi = m; else lo = m + 1; }
    int t_lo = lo;

    float4 acc[DD/128];
    #pragma unroll
    for (int j = 0; j < DD/128; j++) acc[j] = make_float4(0.f, 0.f, 0.f, 0.f);

    double Ap = (t_lo > 0) ? A[t_lo - 1] : 0.0;
    const float4* xb = (const float4*)(x + (size_t)b * SS * DD);

    for (int t = t_lo; t <= t_hi; t++) {
        double At = A[t];
        float w = (float)(fmin(At, kp1) - fmax(Ap, kd));
        Ap = At;
        const float4* row = xb + (size_t)t * (DD/4);
        #pragma unroll
        for (int j = 0; j < DD/128; j++) {
            float4 v = row[lane + 32*j];
            acc[j].x = fmaf(w, v.x, acc[j].x);
            acc[j].y = fmaf(w, v.y, acc[j].y);
            acc[j].z = fmaf(w, v.z, acc[j].z);
            acc[j].w = fmaf(w, v.w, acc[j].w);
        }
    }
    #pragma unroll
    for (int j = 0; j < DD/128; j++) orow[lane + 32*j] = acc[j];
}

// ---------------------------------------------------------------------------
extern "C" void kernel_launch(void* const* d_in, const int* in_sizes, int n_in,
                              void* d_out, int out_size)
{
    const float* x      = (const float*)d_in[0];   // (B,S,D)
    const int*   lens   = (const int*)  d_in[1];   // (B,)
    const float* conv_w = (const float*)d_in[2];   // (D,D,3)
    const float* conv_b = (const float*)d_in[3];   // (D,)
    const float* lin_w  = (const float*)d_in[4];   // (1,D)
    const float* lin_b  = (const float*)d_in[5];   // (1,)
    float* out = (float*)d_out;

    k_prep<<<3*DD/32, 256>>>(conv_w, conv_b, lin_w, lin_b);
    dim3 grid(SS/8, BB);
    k_dots<<<grid, 256>>>(x);
    k_scan<<<BB, SS/2>>>(lens, out, out_size);
    k_gather<<<grid, 256>>>(x, out);
}

// round 7
// speedup vs baseline: 2.0994x; 1.0398x over previous
#include <cuda_runtime.h>
#include <math.h>

// Shapes fixed by the problem.
#define BB 16
#define SS 2048
#define DD 768
#define BSD (BB*SS*DD)

// Scratch (no cudaMalloc allowed).
__device__ double g_dots[(size_t)BB*SS*3];  // per-row dots with w0,w1,w2 (interleaved)
__device__ double g_A[BB*SS];               // per-batch inclusive prefix sums of alpha
__device__ int    g_seg[BB*SS];             // seg_end[k] = first t with A[t] >= k+1
__device__ float  g_weff[3*DD];             // fused conv+linear weights, layout [k*DD + i]
__device__ double g_beff;

// ---------------------------------------------------------------------------
// Kernel 1: fold Linear into Conv.
//   w_eff[k,i] = sum_o lin_w[o] * conv_w[o, i, k]
// Block = 32 columns x 8 o-parts. fp32 chunks of 8 -> fp64, ordered reduce.
// ---------------------------------------------------------------------------
__global__ void k_prep(const float* __restrict__ conv_w,
                       const float* __restrict__ conv_b,
                       const float* __restrict__ lin_w,
                       const float* __restrict__ lin_b)
{
    __shared__ float  slw[DD];
    __shared__ double spart[8][32];
    int tid = threadIdx.x;
    for (int i = tid; i < DD; i += blockDim.x) slw[i] = lin_w[i];
    __syncthreads();

    int lane = tid & 31;
    int part = tid >> 5;                 // 0..7
    int c    = blockIdx.x * 32 + lane;   // column of conv_w

    double acc = 0.0;
    int o0 = part * (DD/8);              // 96 o's per part
    #pragma unroll 2
    for (int o8 = o0; o8 < o0 + DD/8; o8 += 8) {
        float f = 0.0f;
        #pragma unroll
        for (int j = 0; j < 8; j++)
            f = fmaf(slw[o8 + j], conv_w[(size_t)(o8 + j) * (3*DD) + c], f);
        acc += (double)f;
    }
    spart[part][lane] = acc;
    __syncthreads();

    if (part == 0) {
        double s = 0.0;
        #pragma unroll
        for (int p = 0; p < 8; p++) s += spart[p][lane];
        int i = c / 3, k = c - 3*i;
        g_weff[k*DD + i] = (float)s;
    }
    if (blockIdx.x == 0 && part == 1) {   // bias on a different warp
        double acc2 = 0.0;
        for (int o = lane; o < DD; o += 32)
            acc2 += (double)lin_w[o] * (double)conv_b[o];
        #pragma unroll
        for (int off = 16; off; off >>= 1)
            acc2 += __shfl_down_sync(0xffffffffu, acc2, off);
        if (lane == 0) g_beff = acc2 + (double)lin_b[0];
    }
}

// ---------------------------------------------------------------------------
// Kernel 2: per-row dots, TWO rows per warp (12 float4 loads in flight).
//   d_k[b,t] = dot(w_k, x[b,t,:])   k = 0,1,2
// Per-row FMA/accumulation order identical to the passing round-6 kernel.
// ---------------------------------------------------------------------------
__global__ void k_dots(const float* __restrict__ x)
{
    __shared__ float4 sw[3*DD/4];
    for (int i = threadIdx.x; i < 3*DD/4; i += blockDim.x)
        sw[i] = ((const float4*)g_weff)[i];
    __syncthreads();

    int b    = blockIdx.y;
    int pair = blockIdx.x * 8 + (threadIdx.x >> 5);
    int t0   = pair * 2;
    int lane = threadIdx.x & 31;
    const float4* row0 = (const float4*)(x + ((size_t)b * SS + t0) * DD);
    const float4* row1 = row0 + DD/4;

    float4 v0[6], v1[6];
    #pragma unroll
    for (int m = 0; m < 6; m++) v0[m] = row0[lane + 32*m];
    #pragma unroll
    for (int m = 0; m < 6; m++) v1[m] = row1[lane + 32*m];

    double d00 = 0.0, d01 = 0.0, d02 = 0.0;
    double d10 = 0.0, d11 = 0.0, d12 = 0.0;
    #pragma unroll
    for (int m = 0; m < 6; m += 2) {            // chunks of 2 float4 = 8 floats
        float a0 = 0.f, a1 = 0.f, a2 = 0.f;
        float b0 = 0.f, b1 = 0.f, b2 = 0.f;
        #pragma unroll
        for (int mm = m; mm < m + 2; mm++) {
            int idx = lane + 32 * mm;
            float4 w0 = sw[idx];
            float4 w1 = sw[DD/4 + idx];
            float4 w2 = sw[2*(DD/4) + idx];
            a0 = fmaf(w0.x, v0[mm].x, fmaf(w0.y, v0[mm].y, fmaf(w0.z, v0[mm].z, fmaf(w0.w, v0[mm].w, a0))));
            a1 = fmaf(w1.x, v0[mm].x, fmaf(w1.y, v0[mm].y, fmaf(w1.z, v0[mm].z, fmaf(w1.w, v0[mm].w, a1))));
            a2 = fmaf(w2.x, v0[mm].x, fmaf(w2.y, v0[mm].y, fmaf(w2.z, v0[mm].z, fmaf(w2.w, v0[mm].w, a2))));
            b0 = fmaf(w0.x, v1[mm].x, fmaf(w0.y, v1[mm].y, fmaf(w0.z, v1[mm].z, fmaf(w0.w, v1[mm].w, b0))));
            b1 = fmaf(w1.x, v1[mm].x, fmaf(w1.y, v1[mm].y, fmaf(w1.z, v1[mm].z, fmaf(w1.w, v1[mm].w, b1))));
            b2 = fmaf(w2.x, v1[mm].x, fmaf(w2.y, v1[mm].y, fmaf(w2.z, v1[mm].z, fmaf(w2.w, v1[mm].w, b2))));
        }
        d00 += (double)a0; d01 += (double)a1; d02 += (double)a2;
        d10 += (double)b0; d11 += (double)b1; d12 += (double)b2;
    }
    #pragma unroll
    for (int off = 16; off; off >>= 1) {
        d00 += __shfl_down_sync(0xffffffffu, d00, off);
        d01 += __shfl_down_sync(0xffffffffu, d01, off);
        d02 += __shfl_down_sync(0xffffffffu, d02, off);
        d10 += __shfl_down_sync(0xffffffffu, d10, off);
        d11 += __shfl_down_sync(0xffffffffu, d11, off);
        d12 += __shfl_down_sync(0xffffffffu, d12, off);
    }
    if (lane == 0) {
        double* o = g_dots + ((size_t)b * SS + t0) * 3;
        o[0] = d00; o[1] = d01; o[2] = d02;
        o[3] = d10; o[4] = d11; o[5] = d12;
    }
}

// ---------------------------------------------------------------------------
// Kernel 3: fused alpha + per-batch prefix sum (shuffle scan) + segment index.
//   logit[s] = b_eff + d0[s-1] + d1[s] + d2[s+1]
//   alpha[s] = (s < len) ? sigmoid(logit) : 0
// After the scan, detect floor crossings using the SAME stored A values
// (via shared copy) and write g_seg[b][k] = first t with A[t] >= k+1.
// ---------------------------------------------------------------------------
__global__ void k_scan(const int* __restrict__ lens, float* __restrict__ out, int out_size)
{
    __shared__ double swarp[32];
    __shared__ double sincl[SS/2];
    int b    = blockIdx.x;
    int tid  = threadIdx.x;          // 0..1023
    int lane = tid & 31;
    int wid  = tid >> 5;
    int len  = lens[b];
    const double* d = g_dots + (size_t)b * SS * 3;
    double beff = g_beff;

    double a[2];
    #pragma unroll
    for (int e = 0; e < 2; e++) {
        int s = 2*tid + e;
        double z = beff + d[3*s + 1];
        if (s > 0)      z += d[3*(s-1) + 0];
        if (s < SS-1)   z += d[3*(s+1) + 2];
        a[e] = (s < len) ? (1.0 / (1.0 + exp(-z))) : 0.0;
    }
    double psum = a[0] + a[1];

    // inclusive warp scan of psum
    #pragma unroll
    for (int off = 1; off < 32; off <<= 1) {
        double tmp = __shfl_up_sync(0xffffffffu, psum, off);
        if (lane >= off) psum += tmp;
    }
    if (lane == 31) swarp[wid] = psum;
    __syncthreads();
    if (wid == 0) {
        double v = swarp[lane];
        #pragma unroll
        for (int off = 1; off < 32; off <<= 1) {
            double tmp = __shfl_up_sync(0xffffffffu, v, off);
            if (lane >= off) v += tmp;
        }
        swarp[lane] = v;
    }
    __syncthreads();

    double base = (wid > 0) ? swarp[wid - 1] : 0.0;
    double incl = base + psum;             // A[2*tid + 1]  (stored value)
    double A0   = incl - a[1];             // A[2*tid]      (stored value)
    g_A[b*SS + 2*tid]     = A0;
    g_A[b*SS + 2*tid + 1] = incl;
    sincl[tid] = incl;
    __syncthreads();

    // Crossing detection on the stored values (alpha < 1 => floor steps by <= 1).
    double Am1 = (tid > 0) ? sincl[tid - 1] : 0.0;   // A[2*tid - 1] stored
    int f_m1 = (int)floor(Am1);
    int f0   = (int)floor(A0);
    int f1   = (int)floor(incl);
    if (f0 > f_m1) g_seg[b*SS + (f0 - 1)] = 2*tid;
    if (f1 > f0)   g_seg[b*SS + (f1 - 1)] = 2*tid + 1;

    if (tid == SS/2 - 1) {
        int n = f1;
        if (BSD + b < out_size) out[BSD + b] = (float)n;
    }
}

// ---------------------------------------------------------------------------
// Kernel 4: output rows. One warp per (b, k). No binary search:
//   t range is [seg[k-1], seg[k]] (extra boundary step has weight exactly 0).
//   c_k = sum_t ( min(A_t,k+1) - max(A_{t-1},k) ) * h_t
// ---------------------------------------------------------------------------
__global__ void __launch_bounds__(256, 4)
k_gather(const float* __restrict__ x, float* __restrict__ out)
{
    int b    = blockIdx.y;
    int k    = blockIdx.x * 8 + (threadIdx.x >> 5);
    int lane = threadIdx.x & 31;

    const double* A = g_A + (size_t)b * SS;
    int n = (int)floor(A[SS - 1]);

    float4* orow = (float4*)(out + ((size_t)(b * SS + k)) * DD);

    if (k >= n) {
        float4 z = make_float4(0.f, 0.f, 0.f, 0.f);
        #pragma unroll
        for (int j = 0; j < DD/128; j++) orow[lane + 32*j] = z;
        return;
    }

    int t_start = (k > 0) ? g_seg[b*SS + k - 1] : 0;
    int t_end   = g_seg[b*SS + k];

    double kd = (double)k, kp1 = kd + 1.0;

    float4 acc[DD/128];
    #pragma unroll
    for (int j = 0; j < DD/128; j++) acc[j] = make_float4(0.f, 0.f, 0.f, 0.f);

    double Ap = (t_start > 0) ? A[t_start - 1] : 0.0;
    const float4* xb = (const float4*)(x + (size_t)b * SS * DD);

    for (int t = t_start; t <= t_end; t++) {
        double At = A[t];
        float w = (float)(fmin(At, kp1) - fmax(Ap, kd));
        Ap = At;
        const float4* row = xb + (size_t)t * (DD/4);
        #pragma unroll
        for (int j = 0; j < DD/128; j++) {
            float4 v = row[lane + 32*j];
            acc[j].x = fmaf(w, v.x, acc[j].x);
            acc[j].y = fmaf(w, v.y, acc[j].y);
            acc[j].z = fmaf(w, v.z, acc[j].z);
            acc[j].w = fmaf(w, v.w, acc[j].w);
        }
    }
    #pragma unroll
    for (int j = 0; j < DD/128; j++) orow[lane + 32*j] = acc[j];
}

// ---------------------------------------------------------------------------
extern "C" void kernel_launch(void* const* d_in, const int* in_sizes, int n_in,
                              void* d_out, int out_size)
{
    const float* x      = (const float*)d_in[0];   // (B,S,D)
    const int*   lens   = (const int*)  d_in[1];   // (B,)
    const float* conv_w = (const float*)d_in[2];   // (D,D,3)
    const float* conv_b = (const float*)d_in[3];   // (D,)
    const float* lin_w  = (const float*)d_in[4];   // (1,D)
    const float* lin_b  = (const float*)d_in[5];   // (1,)
    float* out = (float*)d_out;

    k_prep<<<3*DD/32, 256>>>(conv_w, conv_b, lin_w, lin_b);
    k_dots<<<dim3(SS/16, BB), 256>>>(x);
    k_scan<<<BB, SS/2>>>(lens, out, out_size);
    k_gather<<<dim3(SS/8, BB), 256>>>(x, out);
}

// round 8
// speedup vs baseline: 2.1061x; 1.0032x over previous
#include <cuda_runtime.h>
#include <math.h>

// Shapes fixed by the problem.
#define BB 16
#define SS 2048
#define DD 768
#define BSD (BB*SS*DD)

#define NBLK 148
#define NTHR 1024
#define NWARP (NBLK*32)

// Scratch (no cudaMalloc allowed).
__device__ double g_dots[(size_t)BB*SS*3];  // per-row dots with w0,w1,w2 (interleaved)
__device__ double g_A[BB*SS];               // per-batch inclusive prefix sums of alpha
__device__ int    g_seg[BB*SS];             // seg_end[k] = first t with A[t] >= k+1
__device__ float  g_weff[3*DD];             // fused conv+linear weights, layout [k*DD + i]
__device__ double g_beff;
__device__ unsigned g_bar[3];               // monotonic barrier counters (persist across replays)

// Grid-wide software barrier. Blocks are co-resident (148 blocks, 1 per SM).
// Counters are monotonic; target rounds up to the next multiple of NBLK, which
// is correct across graph replays because replays are serialized.
__device__ __forceinline__ void grid_sync(int slot) {
    __threadfence();
    __syncthreads();
    if (threadIdx.x == 0) {
        unsigned old = atomicAdd(&g_bar[slot], 1u);
        unsigned target = old - (old % NBLK) + NBLK;
        while (*((volatile unsigned*)&g_bar[slot]) < target)
            __nanosleep(64);
        __threadfence();
    }
    __syncthreads();
}

__global__ void __launch_bounds__(NTHR, 1)
k_fused(const float* __restrict__ x, const int* __restrict__ lens,
        const float* __restrict__ conv_w, const float* __restrict__ conv_b,
        const float* __restrict__ lin_w, const float* __restrict__ lin_b,
        float* __restrict__ out, int out_size)
{
    __shared__ __align__(16) char shraw[12 * 1024];
    int tid  = threadIdx.x;
    int lane = tid & 31;
    int wid  = tid >> 5;
    int wg   = blockIdx.x * 32 + wid;   // global warp id, 0..NWARP-1

    // =====================================================================
    // Phase 1: fold Linear into Conv.  w_eff[k,i] = sum_o lin_w[o]*conv_w[o,i,k]
    // Sub-block of 256 threads handles 32 columns x 8 o-parts (as round-6 k_prep).
    // 72 sub-block tasks; 148 blocks x 4 sub-blocks = 592 available.
    // =====================================================================
    {
        float*  slw   = (float*)shraw;                       // [DD]  3KB
        double* spart = (double*)(shraw + 3072);             // [4][8][32] 8KB
        for (int i = tid; i < DD; i += NTHR) slw[i] = lin_w[i];
        __syncthreads();

        int sub   = tid >> 8;            // 0..3
        int t256  = tid & 255;
        int part  = t256 >> 5;           // 0..7
        int sl    = t256 & 31;
        int sb    = blockIdx.x * 4 + sub;
        if (sb < 72) {
            int c = sb * 32 + sl;        // column of conv_w (= i*3+k)
            double acc = 0.0;
            int o0 = part * (DD/8);      // 96 o's per part
            #pragma unroll 2
            for (int o8 = o0; o8 < o0 + DD/8; o8 += 8) {
                float f = 0.0f;
                #pragma unroll
                for (int j = 0; j < 8; j++)
                    f = fmaf(slw[o8 + j], conv_w[(size_t)(o8 + j) * (3*DD) + c], f);
                acc += (double)f;
            }
            spart[(sub*8 + part)*32 + sl] = acc;
        }
        __syncthreads();
        if (sb < 72 && part == 0) {
            int c = sb * 32 + sl;
            double s = 0.0;
            #pragma unroll
            for (int p = 0; p < 8; p++) s += spart[(sub*8 + p)*32 + sl];
            int i = c / 3, k = c - 3*i;
            g_weff[k*DD + i] = (float)s;
        }
        if (blockIdx.x == 0 && sub == 0 && part == 1) {   // bias
            double acc2 = 0.0;
            for (int o = sl; o < DD; o += 32)
                acc2 += (double)lin_w[o] * (double)conv_b[o];
            #pragma unroll
            for (int off = 16; off; off >>= 1)
                acc2 += __shfl_down_sync(0xffffffffu, acc2, off);
            if (sl == 0) g_beff = acc2 + (double)lin_b[0];
        }
    }
    grid_sync(0);

    // =====================================================================
    // Phase 2: per-row dots (round-6 arithmetic, 1 row/warp, warp-stride).
    //   d_k[b,t] = dot(w_k, x[b,t,:]) for k=0,1,2; x read once.
    // =====================================================================
    {
        float4* sw = (float4*)shraw;     // [3*DD/4] 9KB
        for (int i = tid; i < 3*DD/4; i += NTHR)
            sw[i] = ((const float4*)g_weff)[i];
        __syncthreads();

        for (int r = wg; r < BB*SS; r += NWARP) {
            const float4* row = (const float4*)(x + (size_t)r * DD);
            float4 v[6];
            #pragma unroll
            for (int m = 0; m < 6; m++) v[m] = row[lane + 32*m];

            double d0 = 0.0, d1 = 0.0, d2 = 0.0;
            #pragma unroll
            for (int m = 0; m < 6; m += 2) {
                float f0 = 0.f, f1 = 0.f, f2 = 0.f;
                #pragma unroll
                for (int mm = m; mm < m + 2; mm++) {
                    int idx = lane + 32 * mm;
                    float4 w0 = sw[idx];
                    float4 w1 = sw[DD/4 + idx];
                    float4 w2 = sw[2*(DD/4) + idx];
                    f0 = fmaf(w0.x, v[mm].x, fmaf(w0.y, v[mm].y, fmaf(w0.z, v[mm].z, fmaf(w0.w, v[mm].w, f0))));
                    f1 = fmaf(w1.x, v[mm].x, fmaf(w1.y, v[mm].y, fmaf(w1.z, v[mm].z, fmaf(w1.w, v[mm].w, f1))));
                    f2 = fmaf(w2.x, v[mm].x, fmaf(w2.y, v[mm].y, fmaf(w2.z, v[mm].z, fmaf(w2.w, v[mm].w, f2))));
                }
                d0 += (double)f0; d1 += (double)f1; d2 += (double)f2;
            }
            #pragma unroll
            for (int off = 16; off; off >>= 1) {
                d0 += __shfl_down_sync(0xffffffffu, d0, off);
                d1 += __shfl_down_sync(0xffffffffu, d1, off);
                d2 += __shfl_down_sync(0xffffffffu, d2, off);
            }
            if (lane == 0) {
                double* o = g_dots + (size_t)r * 3;
                o[0] = d0; o[1] = d1; o[2] = d2;
            }
        }
    }
    grid_sync(1);

    // =====================================================================
    // Phase 3: fused alpha + per-batch prefix sum + segment index (blocks 0-15).
    // =====================================================================
    if (blockIdx.x < BB) {
        double* swarp = (double*)shraw;                  // [32]
        double* sincl = (double*)(shraw + 256);          // [SS/2] 8KB
        int b   = blockIdx.x;
        int len = lens[b];
        const double* d = g_dots + (size_t)b * SS * 3;
        double beff = g_beff;

        double a[2];
        #pragma unroll
        for (int e = 0; e < 2; e++) {
            int s = 2*tid + e;
            double z = beff + d[3*s + 1];
            if (s > 0)      z += d[3*(s-1) + 0];
            if (s < SS-1)   z += d[3*(s+1) + 2];
            a[e] = (s < len) ? (1.0 / (1.0 + exp(-z))) : 0.0;
        }
        double psum = a[0] + a[1];

        #pragma unroll
        for (int off = 1; off < 32; off <<= 1) {
            double tmp = __shfl_up_sync(0xffffffffu, psum, off);
            if (lane >= off) psum += tmp;
        }
        if (lane == 31) swarp[wid] = psum;
        __syncthreads();
        if (wid == 0) {
            double v = swarp[lane];
            #pragma unroll
            for (int off = 1; off < 32; off <<= 1) {
                double tmp = __shfl_up_sync(0xffffffffu, v, off);
                if (lane >= off) v += tmp;
            }
            swarp[lane] = v;
        }
        __syncthreads();

        double base = (wid > 0) ? swarp[wid - 1] : 0.0;
        double incl = base + psum;             // A[2*tid + 1]
        double A0   = incl - a[1];             // A[2*tid]
        g_A[b*SS + 2*tid]     = A0;
        g_A[b*SS + 2*tid + 1] = incl;
        sincl[tid] = incl;
        __syncthreads();

        double Am1 = (tid > 0) ? sincl[tid - 1] : 0.0;
        int f_m1 = (int)floor(Am1);
        int f0   = (int)floor(A0);
        int f1   = (int)floor(incl);
        if (f0 > f_m1) g_seg[b*SS + (f0 - 1)] = 2*tid;
        if (f1 > f0)   g_seg[b*SS + (f1 - 1)] = 2*tid + 1;

        if (tid == SS/2 - 1) {
            if (BSD + b < out_size) out[BSD + b] = (float)f1;
        }
    }
    grid_sync(2);

    // =====================================================================
    // Phase 4: gather output rows (round-7 logic, 1 (b,k)/warp, warp-stride).
    // =====================================================================
    for (int task = wg; task < BB*SS; task += NWARP) {
        int b = task >> 11;
        int k = task & (SS - 1);

        const double* A = g_A + (size_t)b * SS;
        int n = (int)floor(A[SS - 1]);

        float4* orow = (float4*)(out + (size_t)task * DD);

        if (k >= n) {
            float4 z = make_float4(0.f, 0.f, 0.f, 0.f);
            #pragma unroll
            for (int j = 0; j < DD/128; j++) orow[lane + 32*j] = z;
            continue;
        }

        int t_start = (k > 0) ? g_seg[b*SS + k - 1] : 0;
        int t_end   = g_seg[b*SS + k];

        double kd = (double)k, kp1 = kd + 1.0;

        float4 acc[DD/128];
        #pragma unroll
        for (int j = 0; j < DD/128; j++) acc[j] = make_float4(0.f, 0.f, 0.f, 0.f);

        double Ap = (t_start > 0) ? A[t_start - 1] : 0.0;
        const float4* xb = (const float4*)(x + (size_t)b * SS * DD);

        for (int t = t_start; t <= t_end; t++) {
            double At = A[t];
            float w = (float)(fmin(At, kp1) - fmax(Ap, kd));
            Ap = At;
            const float4* row = xb + (size_t)t * (DD/4);
            #pragma unroll
            for (int j = 0; j < DD/128; j++) {
                float4 v = row[lane + 32*j];
                acc[j].x = fmaf(w, v.x, acc[j].x);
                acc[j].y = fmaf(w, v.y, acc[j].y);
                acc[j].z = fmaf(w, v.z, acc[j].z);
                acc[j].w = fmaf(w, v.w, acc[j].w);
            }
        }
        #pragma unroll
        for (int j = 0; j < DD/128; j++) orow[lane + 32*j] = acc[j];
    }
}

// ---------------------------------------------------------------------------
extern "C" void kernel_launch(void* const* d_in, const int* in_sizes, int n_in,
                              void* d_out, int out_size)
{
    const float* x      = (const float*)d_in[0];   // (B,S,D)
    const int*   lens   = (const int*)  d_in[1];   // (B,)
    const float* conv_w = (const float*)d_in[2];   // (D,D,3)
    const float* conv_b = (const float*)d_in[3];   // (D,)
    const float* lin_w  = (const float*)d_in[4];   // (1,D)
    const float* lin_b  = (const float*)d_in[5];   // (1,)
    float* out = (float*)d_out;

    k_fused<<<NBLK, NTHR>>>(x, lens, conv_w, conv_b, lin_w, lin_b, out, out_size);
}

// round 9
// speedup vs baseline: 2.9708x; 1.4106x over previous
#include <cuda_runtime.h>
#include <math.h>

// Shapes fixed by the problem.
#define BB 16
#define SS 2048
#define DD 768
#define BSD (BB*SS*DD)

#define NBLK 148
#define NTHR 1024
#define NWARP (NBLK*32)

// Scratch (no cudaMalloc allowed).
__device__ float2 g_dots[(size_t)BB*SS*3]; // per-row dots (hi,lo) with w0,w1,w2
__device__ double g_alpha[BB*SS];          // per-step alphas (fp64)
__device__ double g_A[BB*SS];              // per-batch inclusive prefix sums of alpha
__device__ int    g_seg[BB*SS];            // seg_end[k] = first t with A[t] >= k+1
__device__ float  g_weff[3*DD];            // fused conv+linear weights, layout [k*DD + i]
__device__ double g_beff;
__device__ unsigned g_bar[4];              // monotonic barrier counters (persist across replays)

// Grid-wide software barrier (148 co-resident blocks, 1/SM). Monotonic counters;
// target rounds up to next multiple of NBLK — correct across serialized replays.
__device__ __forceinline__ void grid_sync(int slot) {
    __threadfence();
    __syncthreads();
    if (threadIdx.x == 0) {
        unsigned old = atomicAdd(&g_bar[slot], 1u);
        unsigned target = old - (old % NBLK) + NBLK;
        while (*((volatile unsigned*)&g_bar[slot]) < target)
            __nanosleep(64);
        __threadfence();
    }
    __syncthreads();
}

// Knuth TwoSum: exact error of fp32 add (6 FADD, fp32 pipe only).
__device__ __forceinline__ void two_sum(float a, float b, float& s, float& e) {
    s = a + b;
    float bb = s - a;
    e = (a - (s - bb)) + (b - bb);
}

__global__ void __launch_bounds__(NTHR, 1)
k_fused(const float* __restrict__ x, const int* __restrict__ lens,
        const float* __restrict__ conv_w, const float* __restrict__ conv_b,
        const float* __restrict__ lin_w, const float* __restrict__ lin_b,
        float* __restrict__ out, int out_size)
{
    __shared__ __align__(16) char shraw[12 * 1024];
    int tid  = threadIdx.x;
    int lane = tid & 31;
    int wid  = tid >> 5;
    int wg   = blockIdx.x * 32 + wid;   // global warp id

    // =====================================================================
    // Phase 1: fold Linear into Conv (fp32).  w_eff[k,i] = sum_o lin_w[o]*conv_w[o,i,k]
    // Sub-block of 256 threads: 32 columns x 8 o-parts. fp32 chunk sums,
    // ordered fp32 part reduce (|w_eff| ~ 0.02 -> err ~1e-9, negligible).
    // =====================================================================
    {
        float* slw   = (float*)shraw;                        // [DD]  3KB
        float* spart = (float*)(shraw + 3072);               // [32][32] 4KB
        for (int i = tid; i < DD; i += NTHR) slw[i] = lin_w[i];
        __syncthreads();

        int sub   = tid >> 8;            // 0..3
        int t256  = tid & 255;
        int part  = t256 >> 5;           // 0..7
        int sl    = t256 & 31;
        int sb    = blockIdx.x * 4 + sub;
        if (sb < 72) {
            int c = sb * 32 + sl;        // column of conv_w (= i*3+k)
            float acc = 0.0f;
            int o0 = part * (DD/8);      // 96 o's per part
            #pragma unroll 2
            for (int o8 = o0; o8 < o0 + DD/8; o8 += 8) {
                float f = 0.0f;
                #pragma unroll
                for (int j = 0; j < 8; j++)
                    f = fmaf(slw[o8 + j], conv_w[(size_t)(o8 + j) * (3*DD) + c], f);
                acc += f;
            }
            spart[(sub*8 + part)*32 + sl] = acc;
        }
        __syncthreads();
        if (sb < 72 && part == 0) {
            int c = sb * 32 + sl;
            float s = 0.0f;
            #pragma unroll
            for (int p = 0; p < 8; p++) s += spart[(sub*8 + p)*32 + sl];
            int i = c / 3, k = c - 3*i;
            g_weff[k*DD + i] = s;
        }
        if (blockIdx.x == 0 && sub == 0 && part == 1) {   // bias (tiny fp64, one warp)
            double acc2 = 0.0;
            for (int o = sl; o < DD; o += 32)
                acc2 += (double)lin_w[o] * (double)conv_b[o];
            #pragma unroll
            for (int off = 16; off; off >>= 1)
                acc2 += __shfl_down_sync(0xffffffffu, acc2, off);
            if (sl == 0) g_beff = acc2 + (double)lin_b[0];
        }
    }
    grid_sync(0);

    // =====================================================================
    // Phase 2: per-row dots in df64 (fp32 pipe only). One row per warp.
    //   d_k[b,t] = dot(w_k, x[b,t,:]) for k=0,1,2; x read once.
    // fp32 chunk sums (8 elems) -> TwoSum-compensated (hi,lo) accumulate ->
    // compensated shuffle reduction. Error ~1e-12; ZERO fp64-pipe ops.
    // =====================================================================
    {
        float4* sw = (float4*)shraw;     // [3*DD/4] 9KB
        for (int i = tid; i < 3*DD/4; i += NTHR)
            sw[i] = ((const float4*)g_weff)[i];
        __syncthreads();

        for (int r = wg; r < BB*SS; r += NWARP) {
            const float4* row = (const float4*)(x + (size_t)r * DD);
            float4 v[6];
            #pragma unroll
            for (int m = 0; m < 6; m++) v[m] = row[lane + 32*m];

            float s0 = 0.f, e0 = 0.f, s1 = 0.f, e1 = 0.f, s2 = 0.f, e2 = 0.f;
            #pragma unroll
            for (int m = 0; m < 6; m += 2) {            // chunks of 2 float4 = 8 floats
                float f0 = 0.f, f1 = 0.f, f2 = 0.f;
                #pragma unroll
                for (int mm = m; mm < m + 2; mm++) {
                    int idx = lane + 32 * mm;
                    float4 w0 = sw[idx];
                    float4 w1 = sw[DD/4 + idx];
                    float4 w2 = sw[2*(DD/4) + idx];
                    f0 = fmaf(w0.x, v[mm].x, fmaf(w0.y, v[mm].y, fmaf(w0.z, v[mm].z, fmaf(w0.w, v[mm].w, f0))));
                    f1 = fmaf(w1.x, v[mm].x, fmaf(w1.y, v[mm].y, fmaf(w1.z, v[mm].z, fmaf(w1.w, v[mm].w, f1))));
                    f2 = fmaf(w2.x, v[mm].x, fmaf(w2.y, v[mm].y, fmaf(w2.z, v[mm].z, fmaf(w2.w, v[mm].w, f2))));
                }
                float err;
                two_sum(s0, f0, s0, err); e0 += err;
                two_sum(s1, f1, s1, err); e1 += err;
                two_sum(s2, f2, s2, err); e2 += err;
            }
            // compensated warp reduction
            #pragma unroll
            for (int off = 16; off; off >>= 1) {
                float t0 = __shfl_down_sync(0xffffffffu, s0, off);
                float u0 = __shfl_down_sync(0xffffffffu, e0, off);
                float t1 = __shfl_down_sync(0xffffffffu, s1, off);
                float u1 = __shfl_down_sync(0xffffffffu, e1, off);
                float t2 = __shfl_down_sync(0xffffffffu, s2, off);
                float u2 = __shfl_down_sync(0xffffffffu, e2, off);
                float err;
                two_sum(s0, t0, s0, err); e0 = e0 + u0 + err;
                two_sum(s1, t1, s1, err); e1 = e1 + u1 + err;
                two_sum(s2, t2, s2, err); e2 = e2 + u2 + err;
            }
            if (lane == 0) {
                float2* o = g_dots + (size_t)r * 3;
                o[0] = make_float2(s0, e0);
                o[1] = make_float2(s1, e1);
                o[2] = make_float2(s2, e2);
            }
        }
    }
    grid_sync(1);

    // =====================================================================
    // Phase 2b: alphas, distributed over ALL blocks (fp64 exp cost spread
    // across 148 SMs instead of 16).  logit[s] = b_eff + d0[s-1]+d1[s]+d2[s+1]
    // =====================================================================
    {
        double beff = g_beff;
        int gtid = blockIdx.x * NTHR + tid;
        for (int s = gtid; s < BB*SS; s += NBLK*NTHR) {
            int b   = s >> 11;
            int sin = s & (SS - 1);
            const float2* d = g_dots + (size_t)s * 3;
            float2 d1 = d[1];
            double z = beff + (double)d1.x + (double)d1.y;
            if (sin > 0)    { float2 d0 = d[-3]; z += (double)d0.x + (double)d0.y; }
            if (sin < SS-1) { float2 d2 = d[5];  z += (double)d2.x + (double)d2.y; }
            g_alpha[s] = (sin < lens[b]) ? (1.0 / (1.0 + exp(-z))) : 0.0;
        }
    }
    grid_sync(2);

    // =====================================================================
    // Phase 3: per-batch prefix sum (fp64 adds only) + segment index (blocks 0-15).
    // =====================================================================
    if (blockIdx.x < BB) {
        double* swarp = (double*)shraw;                  // [32]
        double* sincl = (double*)(shraw + 256);          // [SS/2] 8KB
        int b = blockIdx.x;

        double a0v = g_alpha[b*SS + 2*tid];
        double a1v = g_alpha[b*SS + 2*tid + 1];
        double psum = a0v + a1v;

        #pragma unroll
        for (int off = 1; off < 32; off <<= 1) {
            double tmp = __shfl_up_sync(0xffffffffu, psum, off);
            if (lane >= off) psum += tmp;
        }
        if (lane == 31) swarp[wid] = psum;
        __syncthreads();
        if (wid == 0) {
            double v = swarp[lane];
            #pragma unroll
            for (int off = 1; off < 32; off <<= 1) {
                double tmp = __shfl_up_sync(0xffffffffu, v, off);
                if (lane >= off) v += tmp;
            }
            swarp[lane] = v;
        }
        __syncthreads();

        double base = (wid > 0) ? swarp[wid - 1] : 0.0;
        double incl = base + psum;             // A[2*tid + 1]
        double A0   = incl - a1v;              // A[2*tid]
        g_A[b*SS + 2*tid]     = A0;
        g_A[b*SS + 2*tid + 1] = incl;
        sincl[tid] = incl;
        __syncthreads();

        double Am1 = (tid > 0) ? sincl[tid - 1] : 0.0;
        int f_m1 = (int)floor(Am1);
        int f0   = (int)floor(A0);
        int f1   = (int)floor(incl);
        if (f0 > f_m1) g_seg[b*SS + (f0 - 1)] = 2*tid;
        if (f1 > f0)   g_seg[b*SS + (f1 - 1)] = 2*tid + 1;

        if (tid == SS/2 - 1) {
            if (BSD + b < out_size) out[BSD + b] = (float)f1;
        }
    }
    grid_sync(3);

    // =====================================================================
    // Phase 4: gather output rows. One (b,k) per warp, warp-stride.
    //   k >= n -> zeros;  k < n -> c_k over t in [seg[k-1], seg[k]]
    // =====================================================================
    for (int task = wg; task < BB*SS; task += NWARP) {
        int b = task >> 11;
        int k = task & (SS - 1);

        const double* A = g_A + (size_t)b * SS;
        int n = (int)floor(A[SS - 1]);

        float4* orow = (float4*)(out + (size_t)task * DD);

        if (k >= n) {
            float4 z = make_float4(0.f, 0.f, 0.f, 0.f);
            #pragma unroll
            for (int j = 0; j < DD/128; j++) orow[lane + 32*j] = z;
            continue;
        }

        int t_start = (k > 0) ? g_seg[b*SS + k - 1] : 0;
        int t_end   = g_seg[b*SS + k];

        double kd = (double)k, kp1 = kd + 1.0;

        float4 acc[DD/128];
        #pragma unroll
        for (int j = 0; j < DD/128; j++) acc[j] = make_float4(0.f, 0.f, 0.f, 0.f);

        double Ap = (t_start > 0) ? A[t_start - 1] : 0.0;
        const float4* xb = (const float4*)(x + (size_t)b * SS * DD);

        for (int t = t_start; t <= t_end; t++) {
            double At = A[t];
            float w = (float)(fmin(At, kp1) - fmax(Ap, kd));
            Ap = At;
            const float4* row = xb + (size_t)t * (DD/4);
            #pragma unroll
            for (int j = 0; j < DD/128; j++) {
                float4 v = row[lane + 32*j];
                acc[j].x = fmaf(w, v.x, acc[j].x);
                acc[j].y = fmaf(w, v.y, acc[j].y);
                acc[j].z = fmaf(w, v.z, acc[j].z);
                acc[j].w = fmaf(w, v.w, acc[j].w);
            }
        }
        #pragma unroll
        for (int j = 0; j < DD/128; j++) orow[lane + 32*j] = acc[j];
    }
}

// ---------------------------------------------------------------------------
extern "C" void kernel_launch(void* const* d_in, const int* in_sizes, int n_in,
                              void* d_out, int out_size)
{
    const float* x      = (const float*)d_in[0];   // (B,S,D)
    const int*   lens   = (const int*)  d_in[1];   // (B,)
    const float* conv_w = (const float*)d_in[2];   // (D,D,3)
    const float* conv_b = (const float*)d_in[3];   // (D,)
    const float* lin_w  = (const float*)d_in[4];   // (1,D)
    const float* lin_b  = (const float*)d_in[5];   // (1,)
    float* out = (float*)d_out;

    k_fused<<<NBLK, NTHR>>>(x, lens, conv_w, conv_b, lin_w, lin_b, out, out_size);
}